// round 1
// baseline (speedup 1.0000x reference)
#include <cuda_runtime.h>

// Problem constants
constexpr int B_ = 8;     // batch
constexpr int Q_ = 128;   // queries
constexpr int K_ = 1024;  // keys
constexpr int D_ = 512;   // qk feature dim
constexpr int H_ = 256;   // hidden
constexpr int V_ = 512;   // value dim
#define NEG_SCORE (-1e6f)

// Scratch (no cudaMalloc allowed)
__device__ float g_qproj[B_ * Q_ * H_];   // 1 MB
__device__ float g_kproj[B_ * K_ * H_];   // 8 MB
__device__ float g_attn [B_ * Q_ * K_];   // 4 MB

__device__ __forceinline__ float tanh_fast(float x) {
    float y;
    asm("tanh.approx.f32 %0, %1;" : "=f"(y) : "f"(x));
    return y;
}

// ----------------------------------------------------------------------------
// Tiled SGEMM: C[M,N] = A[M,Kd] @ B[Kd,N], all row-major fp32.
// BM=BN=64, BK=16, 256 threads, 4x4 micro-tile per thread.
// blockIdx.z = batch with strides sA/sB/sC (0 for unbatched).
// Requires M%64==0, N%64==0, Kd%16==0 (true for all our shapes).
// ----------------------------------------------------------------------------
__global__ __launch_bounds__(256)
void sgemm64(const float* __restrict__ A, const float* __restrict__ Bm,
             float* __restrict__ C, int M, int N, int Kd,
             long long sA, long long sB, long long sC)
{
    A  += (long long)blockIdx.z * sA;
    Bm += (long long)blockIdx.z * sB;
    C  += (long long)blockIdx.z * sC;

    __shared__ float As[16][68];  // transposed A tile, padded (68*4B keeps 16B align)
    __shared__ float Bs[16][64];

    const int tid  = threadIdx.x;
    const int row0 = blockIdx.y * 64;
    const int col0 = blockIdx.x * 64;

    const int aRow = tid >> 2;          // 0..63
    const int aCol = (tid & 3) << 2;    // 0,4,8,12
    const int bRow = tid >> 4;          // 0..15
    const int bCol = (tid & 15) << 2;   // 0..60
    const int ty = tid >> 4;            // 0..15
    const int tx = tid & 15;            // 0..15

    float acc[4][4];
    #pragma unroll
    for (int i = 0; i < 4; i++)
        #pragma unroll
        for (int j = 0; j < 4; j++) acc[i][j] = 0.0f;

    for (int kb = 0; kb < Kd; kb += 16) {
        float4 av = *(const float4*)(A + (long long)(row0 + aRow) * Kd + kb + aCol);
        As[aCol + 0][aRow] = av.x;
        As[aCol + 1][aRow] = av.y;
        As[aCol + 2][aRow] = av.z;
        As[aCol + 3][aRow] = av.w;
        float4 bv = *(const float4*)(Bm + (long long)(kb + bRow) * N + col0 + bCol);
        *(float4*)&Bs[bRow][bCol] = bv;
        __syncthreads();

        #pragma unroll
        for (int kk = 0; kk < 16; kk++) {
            float4 a4 = *(const float4*)&As[kk][ty << 2];
            float4 b4 = *(const float4*)&Bs[kk][tx << 2];
            float a[4] = {a4.x, a4.y, a4.z, a4.w};
            float b[4] = {b4.x, b4.y, b4.z, b4.w};
            #pragma unroll
            for (int i = 0; i < 4; i++)
                #pragma unroll
                for (int j = 0; j < 4; j++)
                    acc[i][j] = fmaf(a[i], b[j], acc[i][j]);
        }
        __syncthreads();
    }

    #pragma unroll
    for (int i = 0; i < 4; i++) {
        float4 o = make_float4(acc[i][0], acc[i][1], acc[i][2], acc[i][3]);
        *(float4*)(C + (long long)(row0 + ty * 4 + i) * N + col0 + tx * 4) = o;
    }
}

// ----------------------------------------------------------------------------
// Fused additive-score + masked softmax.
// Block = (b, q-tile of 4). 8 warps; warp owns k = wid + 8*t; lane owns 8 h's.
// score[j][k] = sum_h tanh(qproj[b,q0+j,h] + kproj[b,k,h]) * wv[h]
// then masked softmax over k, result -> g_attn.
// ----------------------------------------------------------------------------
__global__ __launch_bounds__(256)
void scores_softmax_kernel(const float* __restrict__ wv, const int* __restrict__ vlens)
{
    constexpr int QT = 4;
    __shared__ float s_sc[QT][K_];     // 16 KB
    __shared__ float s_red[8];

    const int b   = blockIdx.y;
    const int q0  = blockIdx.x * QT;
    const int tid = threadIdx.x;
    const int lane = tid & 31;
    const int wid  = tid >> 5;
    const int h0   = lane * 8;

    // per-lane q slices and wv slice in registers
    float qh[QT][8];
    const float* qp = g_qproj + ((long long)(b * Q_ + q0)) * H_ + h0;
    #pragma unroll
    for (int j = 0; j < QT; j++) {
        float4 a = *(const float4*)(qp + j * H_);
        float4 c = *(const float4*)(qp + j * H_ + 4);
        qh[j][0] = a.x; qh[j][1] = a.y; qh[j][2] = a.z; qh[j][3] = a.w;
        qh[j][4] = c.x; qh[j][5] = c.y; qh[j][6] = c.z; qh[j][7] = c.w;
    }
    float wv8[8];
    {
        float4 a = *(const float4*)(wv + h0);
        float4 c = *(const float4*)(wv + h0 + 4);
        wv8[0] = a.x; wv8[1] = a.y; wv8[2] = a.z; wv8[3] = a.w;
        wv8[4] = c.x; wv8[5] = c.y; wv8[6] = c.z; wv8[7] = c.w;
    }
    const int vlen = vlens[b];

    const float* kbase = g_kproj + (long long)b * K_ * H_ + h0;
    for (int k = wid; k < K_; k += 8) {
        const float* kp = kbase + (long long)k * H_;
        float4 a = *(const float4*)kp;
        float4 c = *(const float4*)(kp + 4);
        float kv[8] = {a.x, a.y, a.z, a.w, c.x, c.y, c.z, c.w};

        float acc0 = 0.f, acc1 = 0.f, acc2 = 0.f, acc3 = 0.f;
        #pragma unroll
        for (int i = 0; i < 8; i++) {
            float t0 = tanh_fast(qh[0][i] + kv[i]);
            float t1 = tanh_fast(qh[1][i] + kv[i]);
            float t2 = tanh_fast(qh[2][i] + kv[i]);
            float t3 = tanh_fast(qh[3][i] + kv[i]);
            acc0 = fmaf(t0, wv8[i], acc0);
            acc1 = fmaf(t1, wv8[i], acc1);
            acc2 = fmaf(t2, wv8[i], acc2);
            acc3 = fmaf(t3, wv8[i], acc3);
        }
        #pragma unroll
        for (int off = 16; off; off >>= 1) {
            acc0 += __shfl_xor_sync(0xffffffffu, acc0, off);
            acc1 += __shfl_xor_sync(0xffffffffu, acc1, off);
            acc2 += __shfl_xor_sync(0xffffffffu, acc2, off);
            acc3 += __shfl_xor_sync(0xffffffffu, acc3, off);
        }
        if (lane < QT) {
            float v = (lane == 0) ? acc0 : (lane == 1) ? acc1 : (lane == 2) ? acc2 : acc3;
            s_sc[lane][k] = (k < vlen) ? v : NEG_SCORE;
        }
    }
    __syncthreads();

    // masked softmax per q row, then write attn
    float* attn_out = g_attn + ((long long)(b * Q_ + q0)) * K_;
    for (int j = 0; j < QT; j++) {
        // max
        float m = -3.4e38f;
        for (int k = tid; k < K_; k += 256) m = fmaxf(m, s_sc[j][k]);
        #pragma unroll
        for (int off = 16; off; off >>= 1)
            m = fmaxf(m, __shfl_xor_sync(0xffffffffu, m, off));
        if (lane == 0) s_red[wid] = m;
        __syncthreads();
        float mm = s_red[0];
        #pragma unroll
        for (int w = 1; w < 8; w++) mm = fmaxf(mm, s_red[w]);
        __syncthreads();

        // exp + sum
        float s = 0.f;
        for (int k = tid; k < K_; k += 256) {
            float e = __expf(s_sc[j][k] - mm);
            s_sc[j][k] = e;
            s += e;
        }
        #pragma unroll
        for (int off = 16; off; off >>= 1)
            s += __shfl_xor_sync(0xffffffffu, s, off);
        if (lane == 0) s_red[wid] = s;
        __syncthreads();
        float ssum = 0.f;
        #pragma unroll
        for (int w = 0; w < 8; w++) ssum += s_red[w];
        float inv = 1.0f / ssum;

        for (int k = tid; k < K_; k += 256)
            attn_out[(long long)j * K_ + k] = s_sc[j][k] * inv;
        __syncthreads();
    }
}

// ----------------------------------------------------------------------------
extern "C" void kernel_launch(void* const* d_in, const int* in_sizes, int n_in,
                              void* d_out, int out_size)
{
    const float* queries = (const float*)d_in[0];  // [B,Q,D]
    const float* keys    = (const float*)d_in[1];  // [B,K,D]
    const float* values  = (const float*)d_in[2];  // [B,K,V]
    const int*   vlens   = (const int*)  d_in[3];  // [B]
    const float* Wq      = (const float*)d_in[4];  // [D,H]
    const float* Wk      = (const float*)d_in[5];  // [D,H]
    const float* wv      = (const float*)d_in[6];  // [H]
    float* out = (float*)d_out;                    // [B,Q,V]

    float *qproj, *kproj, *attn;
    cudaGetSymbolAddress((void**)&qproj, g_qproj);
    cudaGetSymbolAddress((void**)&kproj, g_kproj);
    cudaGetSymbolAddress((void**)&attn,  g_attn);

    dim3 blk(256);

    // q projection: (B*Q x D) @ (D x H)
    sgemm64<<<dim3(H_ / 64, (B_ * Q_) / 64, 1), blk>>>(
        queries, Wq, qproj, B_ * Q_, H_, D_, 0, 0, 0);

    // k projection: (B*K x D) @ (D x H)
    sgemm64<<<dim3(H_ / 64, (B_ * K_) / 64, 1), blk>>>(
        keys, Wk, kproj, B_ * K_, H_, D_, 0, 0, 0);

    // fused tanh-score + masked softmax
    scores_softmax_kernel<<<dim3(Q_ / 4, B_), blk>>>(wv, vlens);

    // out = attn @ values, batched over B
    sgemm64<<<dim3(V_ / 64, Q_ / 64, B_), blk>>>(
        attn, values, out, Q_, V_, K_,
        (long long)Q_ * K_, (long long)K_ * V_, (long long)Q_ * V_);
}